// round 7
// baseline (speedup 1.0000x reference)
#include <cuda_runtime.h>
#include <cuda_fp16.h>

#define NN 100000
#define NE 3200000
#define HH 32
#define OS 40   // g_out row stride (floats): [32 feats | den, sc_sum, sc_cnt, hd1 | pad x4]

#define EMBD 16

// ---------------- device scratch (static, no allocation) ----------------
__device__ __half   g_h[NN * HH];          // layer-1 features (fp16)
__device__ float    g_hs[NN];              // layer-1 h·as
__device__ __align__(16) float g_out[NN * OS];  // agg + aux quad (row = 160B, sector aligned)
__device__ float2   g_sp[NN];              // layer-2 (h2·as2, h2·Wl)
__device__ __align__(16) float g_acc2[NN * 4];  // layer-2 [num, den, hd2, pad]
__device__ float    g_ce[3];               // ce1, ce2, b2·Wl + bl
__device__ float    g_cs[HH];              // W2 · as2
__device__ float    g_cd[HH];              // W2 · ad2
__device__ float    g_cp[HH];              // W2 · Wl

// ---------------- vector reduction helpers (sm_90+) ----------------
__device__ __forceinline__ void red_add_v4(float* p, float4 v) {
    asm volatile("red.global.add.v4.f32 [%0], {%1,%2,%3,%4};"
                 :: "l"(p), "f"(v.x), "f"(v.y), "f"(v.z), "f"(v.w) : "memory");
}
__device__ __forceinline__ void red_add_v2(float* p, float2 v) {
    asm volatile("red.global.add.v2.f32 [%0], {%1,%2};"
                 :: "l"(p), "f"(v.x), "f"(v.y) : "memory");
}

// ---------------- kernels ----------------

__global__ void k_init(const float* We1, const float* ae1,
                       const float* We2, const float* ae2,
                       const float* b2,  const float* Wl, const float* bl,
                       const float* W2,  const float* as2, const float* ad2) {
    int i = blockIdx.x * blockDim.x + threadIdx.x;
    if (i == 0) {
        float c = 0.f;
        for (int j = 0; j < HH; j++) c += We1[j] * ae1[j];
        g_ce[0] = c;
    }
    if (i == 1) {
        float c = 0.f;
        for (int j = 0; j < HH; j++) c += We2[j] * ae2[j];
        g_ce[1] = c;
    }
    if (i == 2) {
        float c = bl[0];
        for (int j = 0; j < HH; j++) c += b2[j] * Wl[j];
        g_ce[2] = c;
    }
    if (i >= 32 && i < 32 + HH) {
        int k = i - 32;
        float cs = 0.f, cd = 0.f, cp = 0.f;
        const float* wr = W2 + k * HH;
        for (int j = 0; j < HH; j++) {
            float w = wr[j];
            cs = fmaf(w, as2[j], cs);
            cd = fmaf(w, ad2[j], cd);
            cp = fmaf(w, Wl[j],  cp);
        }
        g_cs[k] = cs; g_cd[k] = cd; g_cp[k] = cp;
    }
}

// layer-1 node pass: h = emb[x_idx] @ W1 (fp16), hs -> g_hs, hd -> g_out aux pad; zero row
__global__ void k_h1(const int* __restrict__ x_idx, const float* __restrict__ emb,
                     const float* __restrict__ W1, const float* __restrict__ as1,
                     const float* __restrict__ ad1) {
    __shared__ float sW[EMBD * HH];
    __shared__ float sas[HH], sad[HH];
    int t = threadIdx.x;
    for (int i = t; i < EMBD * HH; i += blockDim.x) sW[i] = W1[i];
    if (t < HH) { sas[t] = as1[t]; sad[t] = ad1[t]; }
    __syncthreads();
    int n = (blockIdx.x * blockDim.x + t) >> 5;
    int lane = t & 31;
    if (n >= NN) return;
    int idx = x_idx[n];
    const float* xr = emb + idx * EMBD;
    float acc = 0.f;
#pragma unroll
    for (int k = 0; k < EMBD; k++) acc = fmaf(xr[k], sW[k * HH + lane], acc);
    g_h[n * HH + lane]   = __float2half(acc);
    g_out[n * OS + lane] = 0.f;
    float s = acc * sas[lane];
    float d = acc * sad[lane];
    for (int o = 16; o; o >>= 1) {
        s += __shfl_xor_sync(0xffffffffu, s, o);
        d += __shfl_xor_sync(0xffffffffu, d, o);
    }
    if (lane == 0) {
        g_hs[n] = s;
        // aux quad: [den=0, sc_sum=0, sc_cnt=0, hd1]  (hd1 slot only ever gains +0)
        *reinterpret_cast<float4*>(g_out + n * OS + 32) = make_float4(0.f, 0.f, 0.f, d);
    }
}

// layer-1 fused edge pass, 8 lanes/edge; ex once per edge (lane q==0):
//   out[d,0:32] += ex*h[s,:]  ;  aux[d] += (ex, ea, 1, 0)  ; hd1 read from aux pad
__global__ void k_edge1(const int* __restrict__ src, const int* __restrict__ dst,
                        const float* __restrict__ ea) {
    long long t = (long long)blockIdx.x * blockDim.x + threadIdx.x;
    int e = (int)(t >> 3);
    if (e >= NE) return;
    int lane = threadIdx.x & 31;
    int q = lane & 7;
    int s = src[e], d = dst[e];
    float ex;
    if (q == 0) {
        float a  = ea[e];
        float hd = g_out[d * OS + 35];              // same sector as the aux RMW below
        float al = g_hs[s] + hd + a * g_ce[0];
        al = (al > 0.f) ? al : 0.2f * al;
        ex = __expf(al);
        red_add_v4(g_out + d * OS + 32, make_float4(ex, a, 1.f, 0.f));
    }
    ex = __shfl_sync(0xffffffffu, ex, lane & ~7);   // full grid multiple -> all lanes alive
    const __half2* hp = reinterpret_cast<const __half2*>(g_h + s * HH + q * 4);
    float2 h01 = __half22float2(hp[0]);
    float2 h23 = __half22float2(hp[1]);
    float4 hv = make_float4(h01.x * ex, h01.y * ex, h23.x * ex, h23.y * ex);
    red_add_v4(g_out + d * OS + q * 4, hv);
}

// normalize layer 1 (+ self-loop), relu(.+b1); collapsed layer-2 projections
__global__ void k_mid(const float* __restrict__ b1) {
    int t = threadIdx.x;
    int n = (blockIdx.x * blockDim.x + t) >> 5;
    int lane = t & 31;
    if (n >= NN) return;
    float4 aux = make_float4(0.f, 0.f, 0.f, 0.f);
    if (lane == 0)
        aux = *reinterpret_cast<const float4*>(g_out + n * OS + 32);
    float den  = __shfl_sync(0xffffffffu, aux.x, 0);
    float scx  = __shfl_sync(0xffffffffu, aux.y, 0);
    float scc  = __shfl_sync(0xffffffffu, aux.z, 0);
    float hd1  = __shfl_sync(0xffffffffu, aux.w, 0);
    float loop = scx / fmaxf(scc, 1.f);
    float al = g_hs[n] + hd1 + loop * g_ce[0];
    al = (al > 0.f) ? al : 0.2f * al;
    float exs = __expf(al);
    float hn = __half2float(g_h[n * HH + lane]);
    float v = (g_out[n * OS + lane] + exs * hn) / (den + exs + 1e-16f);
    v = fmaxf(v + b1[lane], 0.f);
    float s = v * g_cs[lane];
    float d = v * g_cd[lane];
    float p = v * g_cp[lane];
    for (int o = 16; o; o >>= 1) {
        s += __shfl_xor_sync(0xffffffffu, s, o);
        d += __shfl_xor_sync(0xffffffffu, d, o);
        p += __shfl_xor_sync(0xffffffffu, p, o);
    }
    if (lane == 0) {
        g_sp[n] = make_float2(s, p);
        // acc2 quad: [num=0, den=0, hd2, pad]
        *reinterpret_cast<float4*>(g_acc2 + n * 4) = make_float4(0.f, 0.f, d, 0.f);
    }
}

// layer-2 edge pass, 1 thread/edge (scalar projection); hd2 shares sector with RMW
__global__ void k_edge2(const int* __restrict__ src, const int* __restrict__ dst,
                        const float* __restrict__ ea) {
    int e = blockIdx.x * blockDim.x + threadIdx.x;
    if (e >= NE) return;
    int s = src[e], d = dst[e];
    float2 sp = g_sp[s];
    float hd2 = g_acc2[d * 4 + 2];
    float al = sp.x + hd2 + ea[e] * g_ce[1];
    al = (al > 0.f) ? al : 0.2f * al;
    float ex = __expf(al);
    red_add_v2(g_acc2 + d * 4, make_float2(ex * sp.y, ex));
}

// final: add self-loop, normalize, add (b2·Wl + bl)
__global__ void k_final(float* __restrict__ out) {
    int n = blockIdx.x * blockDim.x + threadIdx.x;
    if (n >= NN) return;
    float4 aux = *reinterpret_cast<const float4*>(g_out + n * OS + 32);
    float loop = aux.y / fmaxf(aux.z, 1.f);
    float4 acc = *reinterpret_cast<const float4*>(g_acc2 + n * 4);
    float2 sp  = g_sp[n];
    float al = sp.x + acc.z + loop * g_ce[1];
    al = (al > 0.f) ? al : 0.2f * al;
    float exs = __expf(al);
    out[n] = (acc.x + exs * sp.y) / (acc.y + exs + 1e-16f) + g_ce[2];
}

// ---------------- launch ----------------
extern "C" void kernel_launch(void* const* d_in, const int* in_sizes, int n_in,
                              void* d_out, int out_size) {
    const int*   x_idx = (const int*)  d_in[0];
    const int*   ei    = (const int*)  d_in[1];
    const float* ea    = (const float*)d_in[2];
    const float* emb   = (const float*)d_in[3];
    const float* W1    = (const float*)d_in[4];
    const float* as1   = (const float*)d_in[5];
    const float* ad1   = (const float*)d_in[6];
    const float* We1   = (const float*)d_in[7];
    const float* ae1   = (const float*)d_in[8];
    const float* b1    = (const float*)d_in[9];
    const float* W2    = (const float*)d_in[10];
    const float* as2   = (const float*)d_in[11];
    const float* ad2   = (const float*)d_in[12];
    const float* We2   = (const float*)d_in[13];
    const float* ae2   = (const float*)d_in[14];
    const float* b2    = (const float*)d_in[15];
    const float* Wl    = (const float*)d_in[16];
    const float* bl    = (const float*)d_in[17];
    float* out = (float*)d_out;

    const int* src = ei;
    const int* dst = ei + NE;

    const int TB = 256;
    const int gN   = (NN + TB - 1) / TB;
    const int gE   = (NE + TB - 1) / TB;
    const int gNW  = (NN * 32 + TB - 1) / TB;                     // warp per node
    const int gED1 = (int)(((long long)NE * 8 + TB - 1) / TB);    // 8 lanes per edge

    k_init<<<1, 64>>>(We1, ae1, We2, ae2, b2, Wl, bl, W2, as2, ad2);

    // layer 1
    k_h1<<<gNW, TB>>>(x_idx, emb, W1, as1, ad1);
    k_edge1<<<gED1, TB>>>(src, dst, ea);

    // layer 2 (collapsed to scalar projections)
    k_mid<<<gNW, TB>>>(b1);
    k_edge2<<<gE, TB>>>(src, dst, ea);

    k_final<<<gN, TB>>>(out);
}

// round 8
// speedup vs baseline: 1.0835x; 1.0835x over previous
#include <cuda_runtime.h>
#include <cuda_fp16.h>

#define NN 100000
#define NE 3200000
#define HH 32
#define OS 40   // g_out row stride (floats): [32 feats | den, sc_sum, sc_cnt, pad | pad x4] = 160B

#define EMBD 16

// ---------------- device scratch (static, no allocation) ----------------
__device__ __half   g_h[NN * HH];               // layer-1 features (fp16)
__device__ float    g_hs[NN];                   // layer-1 h·as
__device__ float    g_hd[NN];                   // layer-1 h·ad, reused for layer-2 h2·ad2
__device__ __align__(16) float g_out[NN * OS];  // agg + aux quad, rows sector-aligned
__device__ float2   g_sp[NN];                   // layer-2 (h2·as2, h2·Wl)
__device__ float2   g_acc2[NN];                 // layer-2 (num, den)
__device__ float    g_ce[3];                    // ce1, ce2, b2·Wl + bl
__device__ float    g_cs[HH];                   // W2 · as2
__device__ float    g_cd[HH];                   // W2 · ad2
__device__ float    g_cp[HH];                   // W2 · Wl

// ---------------- vector reduction helpers (sm_90+) ----------------
__device__ __forceinline__ void red_add_v4(float* p, float4 v) {
    asm volatile("red.global.add.v4.f32 [%0], {%1,%2,%3,%4};"
                 :: "l"(p), "f"(v.x), "f"(v.y), "f"(v.z), "f"(v.w) : "memory");
}
__device__ __forceinline__ void red_add_v2(float* p, float2 v) {
    asm volatile("red.global.add.v2.f32 [%0], {%1,%2};"
                 :: "l"(p), "f"(v.x), "f"(v.y) : "memory");
}

// ---------------- kernels ----------------

// zero g_out (features + aux) with wide streaming stores
__global__ void k_zero() {
    int i = blockIdx.x * blockDim.x + threadIdx.x;
    float4 z = make_float4(0.f, 0.f, 0.f, 0.f);
    if (i < NN * OS / 4)
        reinterpret_cast<float4*>(g_out)[i] = z;
}

__global__ void k_init(const float* We1, const float* ae1,
                       const float* We2, const float* ae2,
                       const float* b2,  const float* Wl, const float* bl,
                       const float* W2,  const float* as2, const float* ad2) {
    int i = blockIdx.x * blockDim.x + threadIdx.x;
    if (i == 0) {
        float c = 0.f;
        for (int j = 0; j < HH; j++) c += We1[j] * ae1[j];
        g_ce[0] = c;
    }
    if (i == 1) {
        float c = 0.f;
        for (int j = 0; j < HH; j++) c += We2[j] * ae2[j];
        g_ce[1] = c;
    }
    if (i == 2) {
        float c = bl[0];
        for (int j = 0; j < HH; j++) c += b2[j] * Wl[j];
        g_ce[2] = c;
    }
    if (i >= 32 && i < 32 + HH) {
        int k = i - 32;
        float cs = 0.f, cd = 0.f, cp = 0.f;
        const float* wr = W2 + k * HH;
        for (int j = 0; j < HH; j++) {
            float w = wr[j];
            cs = fmaf(w, as2[j], cs);
            cd = fmaf(w, ad2[j], cd);
            cp = fmaf(w, Wl[j],  cp);
        }
        g_cs[k] = cs; g_cd[k] = cd; g_cp[k] = cp;
    }
}

// layer-1 node pass: h = emb[x_idx] @ W1 (fp16), hs/hd  (g_out zeroed by k_zero)
__global__ void k_h1(const int* __restrict__ x_idx, const float* __restrict__ emb,
                     const float* __restrict__ W1, const float* __restrict__ as1,
                     const float* __restrict__ ad1) {
    __shared__ float sW[EMBD * HH];
    __shared__ float sas[HH], sad[HH];
    int t = threadIdx.x;
    for (int i = t; i < EMBD * HH; i += blockDim.x) sW[i] = W1[i];
    if (t < HH) { sas[t] = as1[t]; sad[t] = ad1[t]; }
    __syncthreads();
    int n = (blockIdx.x * blockDim.x + t) >> 5;
    int lane = t & 31;
    if (n >= NN) return;
    int idx = x_idx[n];
    const float* xr = emb + idx * EMBD;
    float acc = 0.f;
#pragma unroll
    for (int k = 0; k < EMBD; k++) acc = fmaf(xr[k], sW[k * HH + lane], acc);
    g_h[n * HH + lane] = __float2half(acc);
    float s = acc * sas[lane];
    float d = acc * sad[lane];
    for (int o = 16; o; o >>= 1) {
        s += __shfl_xor_sync(0xffffffffu, s, o);
        d += __shfl_xor_sync(0xffffffffu, d, o);
    }
    if (lane == 0) { g_hs[n] = s; g_hd[n] = d; }
}

// layer-1 fused edge pass, 8 lanes/edge; ex once per edge (lane q==0):
//   out[d,0:32] += ex*h[s,:]  ;  aux[d] += (ex, ea, 1, 0)   [single RMW sector]
__global__ void k_edge1(const int* __restrict__ src, const int* __restrict__ dst,
                        const float* __restrict__ ea) {
    long long t = (long long)blockIdx.x * blockDim.x + threadIdx.x;
    int e = (int)(t >> 3);
    if (e >= NE) return;
    int lane = threadIdx.x & 31;
    int q = lane & 7;
    int s = src[e], d = dst[e];
    float ex;
    if (q == 0) {
        float a  = ea[e];
        float al = g_hs[s] + g_hd[d] + a * g_ce[0];   // hd from cold read-only array
        al = (al > 0.f) ? al : 0.2f * al;
        ex = __expf(al);
        red_add_v4(g_out + d * OS + 32, make_float4(ex, a, 1.f, 0.f));
    }
    ex = __shfl_sync(0xffffffffu, ex, lane & ~7);     // grid exact multiple: all lanes alive
    const __half2* hp = reinterpret_cast<const __half2*>(g_h + s * HH + q * 4);
    float2 h01 = __half22float2(hp[0]);
    float2 h23 = __half22float2(hp[1]);
    float4 hv = make_float4(h01.x * ex, h01.y * ex, h23.x * ex, h23.y * ex);
    red_add_v4(g_out + d * OS + q * 4, hv);
}

// normalize layer 1 (+ self-loop), relu(.+b1); collapsed layer-2 projections
__global__ void k_mid(const float* __restrict__ b1) {
    int t = threadIdx.x;
    int n = (blockIdx.x * blockDim.x + t) >> 5;
    int lane = t & 31;
    if (n >= NN) return;
    float4 aux = make_float4(0.f, 0.f, 0.f, 0.f);
    if (lane == 0)
        aux = *reinterpret_cast<const float4*>(g_out + n * OS + 32);
    float den  = __shfl_sync(0xffffffffu, aux.x, 0);
    float scx  = __shfl_sync(0xffffffffu, aux.y, 0);
    float scc  = __shfl_sync(0xffffffffu, aux.z, 0);
    float loop = scx / fmaxf(scc, 1.f);
    float al = g_hs[n] + g_hd[n] + loop * g_ce[0];
    al = (al > 0.f) ? al : 0.2f * al;
    float exs = __expf(al);
    float hn = __half2float(g_h[n * HH + lane]);
    float v = (g_out[n * OS + lane] + exs * hn) / (den + exs + 1e-16f);
    v = fmaxf(v + b1[lane], 0.f);
    float s = v * g_cs[lane];
    float d = v * g_cd[lane];
    float p = v * g_cp[lane];
    for (int o = 16; o; o >>= 1) {
        s += __shfl_xor_sync(0xffffffffu, s, o);
        d += __shfl_xor_sync(0xffffffffu, d, o);
        p += __shfl_xor_sync(0xffffffffu, p, o);
    }
    if (lane == 0) {
        g_sp[n] = make_float2(s, p);
        g_hd[n] = d;                       // reuse for layer 2
        g_acc2[n] = make_float2(0.f, 0.f);
    }
}

// layer-2 edge pass, 1 thread/edge (scalar projection); hd2 from read-only array
__global__ void k_edge2(const int* __restrict__ src, const int* __restrict__ dst,
                        const float* __restrict__ ea) {
    int e = blockIdx.x * blockDim.x + threadIdx.x;
    if (e >= NE) return;
    int s = src[e], d = dst[e];
    float2 sp = g_sp[s];
    float al = sp.x + g_hd[d] + ea[e] * g_ce[1];
    al = (al > 0.f) ? al : 0.2f * al;
    float ex = __expf(al);
    red_add_v2(&g_acc2[d].x, make_float2(ex * sp.y, ex));
}

// final: add self-loop, normalize, add (b2·Wl + bl)
__global__ void k_final(float* __restrict__ out) {
    int n = blockIdx.x * blockDim.x + threadIdx.x;
    if (n >= NN) return;
    float4 aux = *reinterpret_cast<const float4*>(g_out + n * OS + 32);
    float loop = aux.y / fmaxf(aux.z, 1.f);
    float2 sp  = g_sp[n];
    float al = sp.x + g_hd[n] + loop * g_ce[1];
    al = (al > 0.f) ? al : 0.2f * al;
    float exs = __expf(al);
    float2 acc = g_acc2[n];
    out[n] = (acc.x + exs * sp.y) / (acc.y + exs + 1e-16f) + g_ce[2];
}

// ---------------- launch ----------------
extern "C" void kernel_launch(void* const* d_in, const int* in_sizes, int n_in,
                              void* d_out, int out_size) {
    const int*   x_idx = (const int*)  d_in[0];
    const int*   ei    = (const int*)  d_in[1];
    const float* ea    = (const float*)d_in[2];
    const float* emb   = (const float*)d_in[3];
    const float* W1    = (const float*)d_in[4];
    const float* as1   = (const float*)d_in[5];
    const float* ad1   = (const float*)d_in[6];
    const float* We1   = (const float*)d_in[7];
    const float* ae1   = (const float*)d_in[8];
    const float* b1    = (const float*)d_in[9];
    const float* W2    = (const float*)d_in[10];
    const float* as2   = (const float*)d_in[11];
    const float* ad2   = (const float*)d_in[12];
    const float* We2   = (const float*)d_in[13];
    const float* ae2   = (const float*)d_in[14];
    const float* b2    = (const float*)d_in[15];
    const float* Wl    = (const float*)d_in[16];
    const float* bl    = (const float*)d_in[17];
    float* out = (float*)d_out;

    const int* src = ei;
    const int* dst = ei + NE;

    const int TB = 256;
    const int gN   = (NN + TB - 1) / TB;
    const int gE   = (NE + TB - 1) / TB;
    const int gNW  = (NN * 32 + TB - 1) / TB;                     // warp per node
    const int gED1 = (int)(((long long)NE * 8 + TB - 1) / TB);    // 8 lanes per edge
    const int gZ   = (NN * OS / 4 + TB - 1) / TB;

    k_zero<<<gZ, TB>>>();
    k_init<<<1, 64>>>(We1, ae1, We2, ae2, b2, Wl, bl, W2, as2, ad2);

    // layer 1
    k_h1<<<gNW, TB>>>(x_idx, emb, W1, as1, ad1);
    k_edge1<<<gED1, TB>>>(src, dst, ea);

    // layer 2 (collapsed to scalar projections)
    k_mid<<<gNW, TB>>>(b1);
    k_edge2<<<gE, TB>>>(src, dst, ea);

    k_final<<<gN, TB>>>(out);
}

// round 9
// speedup vs baseline: 1.0860x; 1.0023x over previous
#include <cuda_runtime.h>
#include <cuda_fp16.h>

#define NN 100000
#define NE 3200000
#define HH 32
#define OS 64   // g_out row stride (floats): 256B rows, 128B-line aligned
                // [0..31] features | [32..35] aux (den, sc_sum, sc_cnt, pad) | rest pad

#define EMBD 16

// ---------------- device scratch (static, no allocation) ----------------
__device__ __half   g_h[NN * HH];               // layer-1 features (fp16)
__device__ float    g_hs[NN];                   // layer-1 h·as
__device__ float    g_hd[NN];                   // layer-1 h·ad, reused for layer-2 h2·ad2
__device__ __align__(256) float g_out[NN * OS]; // agg + aux, line-aligned rows
__device__ float2   g_sp[NN];                   // layer-2 (h2·as2, h2·Wl)
__device__ float2   g_acc2[NN];                 // layer-2 (num, den)
__device__ float    g_ce[3];                    // ce1, ce2, b2·Wl + bl
__device__ float    g_cs[HH];                   // W2 · as2
__device__ float    g_cd[HH];                   // W2 · ad2
__device__ float    g_cp[HH];                   // W2 · Wl

// ---------------- vector reduction helpers (sm_90+) ----------------
__device__ __forceinline__ void red_add_v4(float* p, float4 v) {
    asm volatile("red.global.add.v4.f32 [%0], {%1,%2,%3,%4};"
                 :: "l"(p), "f"(v.x), "f"(v.y), "f"(v.z), "f"(v.w) : "memory");
}
__device__ __forceinline__ void red_add_v2(float* p, float2 v) {
    asm volatile("red.global.add.v2.f32 [%0], {%1,%2};"
                 :: "l"(p), "f"(v.x), "f"(v.y) : "memory");
}

// ---------------- kernels ----------------

// zero the used 36 floats of each g_out row (9 float4 per row)
__global__ void k_zero() {
    int i = blockIdx.x * blockDim.x + threadIdx.x;
    if (i >= NN * 9) return;
    int r = i / 9, j = i % 9;
    reinterpret_cast<float4*>(g_out + r * OS)[j] = make_float4(0.f, 0.f, 0.f, 0.f);
}

__global__ void k_init(const float* We1, const float* ae1,
                       const float* We2, const float* ae2,
                       const float* b2,  const float* Wl, const float* bl,
                       const float* W2,  const float* as2, const float* ad2) {
    int i = blockIdx.x * blockDim.x + threadIdx.x;
    if (i == 0) {
        float c = 0.f;
        for (int j = 0; j < HH; j++) c += We1[j] * ae1[j];
        g_ce[0] = c;
    }
    if (i == 1) {
        float c = 0.f;
        for (int j = 0; j < HH; j++) c += We2[j] * ae2[j];
        g_ce[1] = c;
    }
    if (i == 2) {
        float c = bl[0];
        for (int j = 0; j < HH; j++) c += b2[j] * Wl[j];
        g_ce[2] = c;
    }
    if (i >= 32 && i < 32 + HH) {
        int k = i - 32;
        float cs = 0.f, cd = 0.f, cp = 0.f;
        const float* wr = W2 + k * HH;
        for (int j = 0; j < HH; j++) {
            float w = wr[j];
            cs = fmaf(w, as2[j], cs);
            cd = fmaf(w, ad2[j], cd);
            cp = fmaf(w, Wl[j],  cp);
        }
        g_cs[k] = cs; g_cd[k] = cd; g_cp[k] = cp;
    }
}

// layer-1 node pass: h = emb[x_idx] @ W1 (fp16), hs/hd
__global__ void k_h1(const int* __restrict__ x_idx, const float* __restrict__ emb,
                     const float* __restrict__ W1, const float* __restrict__ as1,
                     const float* __restrict__ ad1) {
    __shared__ float sW[EMBD * HH];
    __shared__ float sas[HH], sad[HH];
    int t = threadIdx.x;
    for (int i = t; i < EMBD * HH; i += blockDim.x) sW[i] = W1[i];
    if (t < HH) { sas[t] = as1[t]; sad[t] = ad1[t]; }
    __syncthreads();
    int n = (blockIdx.x * blockDim.x + t) >> 5;
    int lane = t & 31;
    if (n >= NN) return;
    int idx = x_idx[n];
    const float* xr = emb + idx * EMBD;
    float acc = 0.f;
#pragma unroll
    for (int k = 0; k < EMBD; k++) acc = fmaf(xr[k], sW[k * HH + lane], acc);
    g_h[n * HH + lane] = __float2half(acc);
    float s = acc * sas[lane];
    float d = acc * sad[lane];
    for (int o = 16; o; o >>= 1) {
        s += __shfl_xor_sync(0xffffffffu, s, o);
        d += __shfl_xor_sync(0xffffffffu, d, o);
    }
    if (lane == 0) { g_hs[n] = s; g_hd[n] = d; }
}

// layer-1 fused edge pass, 8 lanes/edge; ex once per edge (lane q==0):
//   out[d,0:32] += ex*h[s,:]  (one 128B line)  ;  aux[d] += (ex, ea, 1, 0)
__global__ void k_edge1(const int* __restrict__ src, const int* __restrict__ dst,
                        const float* __restrict__ ea) {
    long long t = (long long)blockIdx.x * blockDim.x + threadIdx.x;
    int e = (int)(t >> 3);
    if (e >= NE) return;
    int lane = threadIdx.x & 31;
    int q = lane & 7;
    int s = src[e], d = dst[e];
    float ex;
    if (q == 0) {
        float a  = ea[e];
        float al = g_hs[s] + g_hd[d] + a * g_ce[0];
        al = (al > 0.f) ? al : 0.2f * al;
        ex = __expf(al);
        red_add_v4(g_out + d * OS + 32, make_float4(ex, a, 1.f, 0.f));
    }
    ex = __shfl_sync(0xffffffffu, ex, lane & ~7);   // grid exact multiple: all lanes alive
    // single 8B gather of 4 fp16 features
    uint2 raw = *reinterpret_cast<const uint2*>(g_h + s * HH + q * 4);
    float2 h01 = __half22float2(*reinterpret_cast<const __half2*>(&raw.x));
    float2 h23 = __half22float2(*reinterpret_cast<const __half2*>(&raw.y));
    float4 hv = make_float4(h01.x * ex, h01.y * ex, h23.x * ex, h23.y * ex);
    red_add_v4(g_out + d * OS + q * 4, hv);
}

// normalize layer 1 (+ self-loop), relu(.+b1); collapsed layer-2 projections
__global__ void k_mid(const float* __restrict__ b1) {
    int t = threadIdx.x;
    int n = (blockIdx.x * blockDim.x + t) >> 5;
    int lane = t & 31;
    if (n >= NN) return;
    float4 aux = make_float4(0.f, 0.f, 0.f, 0.f);
    if (lane == 0)
        aux = *reinterpret_cast<const float4*>(g_out + n * OS + 32);
    float den  = __shfl_sync(0xffffffffu, aux.x, 0);
    float scx  = __shfl_sync(0xffffffffu, aux.y, 0);
    float scc  = __shfl_sync(0xffffffffu, aux.z, 0);
    float loop = scx / fmaxf(scc, 1.f);
    float al = g_hs[n] + g_hd[n] + loop * g_ce[0];
    al = (al > 0.f) ? al : 0.2f * al;
    float exs = __expf(al);
    float hn = __half2float(g_h[n * HH + lane]);
    float v = (g_out[n * OS + lane] + exs * hn) / (den + exs + 1e-16f);
    v = fmaxf(v + b1[lane], 0.f);
    float s = v * g_cs[lane];
    float d = v * g_cd[lane];
    float p = v * g_cp[lane];
    for (int o = 16; o; o >>= 1) {
        s += __shfl_xor_sync(0xffffffffu, s, o);
        d += __shfl_xor_sync(0xffffffffu, d, o);
        p += __shfl_xor_sync(0xffffffffu, p, o);
    }
    if (lane == 0) {
        g_sp[n] = make_float2(s, p);
        g_hd[n] = d;
        g_acc2[n] = make_float2(0.f, 0.f);
    }
}

// layer-2 edge pass, 1 thread/edge (scalar projection)
__global__ void k_edge2(const int* __restrict__ src, const int* __restrict__ dst,
                        const float* __restrict__ ea) {
    int e = blockIdx.x * blockDim.x + threadIdx.x;
    if (e >= NE) return;
    int s = src[e], d = dst[e];
    float2 sp = g_sp[s];
    float al = sp.x + g_hd[d] + ea[e] * g_ce[1];
    al = (al > 0.f) ? al : 0.2f * al;
    float ex = __expf(al);
    red_add_v2(&g_acc2[d].x, make_float2(ex * sp.y, ex));
}

// final: add self-loop, normalize, add (b2·Wl + bl)
__global__ void k_final(float* __restrict__ out) {
    int n = blockIdx.x * blockDim.x + threadIdx.x;
    if (n >= NN) return;
    float4 aux = *reinterpret_cast<const float4*>(g_out + n * OS + 32);
    float loop = aux.y / fmaxf(aux.z, 1.f);
    float2 sp  = g_sp[n];
    float al = sp.x + g_hd[n] + loop * g_ce[1];
    al = (al > 0.f) ? al : 0.2f * al;
    float exs = __expf(al);
    float2 acc = g_acc2[n];
    out[n] = (acc.x + exs * sp.y) / (acc.y + exs + 1e-16f) + g_ce[2];
}

// ---------------- launch ----------------
extern "C" void kernel_launch(void* const* d_in, const int* in_sizes, int n_in,
                              void* d_out, int out_size) {
    const int*   x_idx = (const int*)  d_in[0];
    const int*   ei    = (const int*)  d_in[1];
    const float* ea    = (const float*)d_in[2];
    const float* emb   = (const float*)d_in[3];
    const float* W1    = (const float*)d_in[4];
    const float* as1   = (const float*)d_in[5];
    const float* ad1   = (const float*)d_in[6];
    const float* We1   = (const float*)d_in[7];
    const float* ae1   = (const float*)d_in[8];
    const float* b1    = (const float*)d_in[9];
    const float* W2    = (const float*)d_in[10];
    const float* as2   = (const float*)d_in[11];
    const float* ad2   = (const float*)d_in[12];
    const float* We2   = (const float*)d_in[13];
    const float* ae2   = (const float*)d_in[14];
    const float* b2    = (const float*)d_in[15];
    const float* Wl    = (const float*)d_in[16];
    const float* bl    = (const float*)d_in[17];
    float* out = (float*)d_out;

    const int* src = ei;
    const int* dst = ei + NE;

    const int TB = 256;
    const int gN   = (NN + TB - 1) / TB;
    const int gE   = (NE + TB - 1) / TB;
    const int gNW  = (NN * 32 + TB - 1) / TB;                     // warp per node
    const int gED1 = (int)(((long long)NE * 8 + TB - 1) / TB);    // 8 lanes per edge
    const int gZ   = (NN * 9 + TB - 1) / TB;

    k_zero<<<gZ, TB>>>();
    k_init<<<1, 64>>>(We1, ae1, We2, ae2, b2, Wl, bl, W2, as2, ad2);

    // layer 1
    k_h1<<<gNW, TB>>>(x_idx, emb, W1, as1, ad1);
    k_edge1<<<gED1, TB>>>(src, dst, ea);

    // layer 2 (collapsed to scalar projections)
    k_mid<<<gNW, TB>>>(b1);
    k_edge2<<<gE, TB>>>(src, dst, ea);

    k_final<<<gN, TB>>>(out);
}